// round 1
// baseline (speedup 1.0000x reference)
#include <cuda_runtime.h>
#include <cuda_bf16.h>

// BundleAdjustment: fused reprojection-residual kernel.
// Inputs (metadata order):
//  0 poses            (1, 8192, 7)   f32   57344
//  1 init_poses       (1, 8192, 7)   f32   57344
//  2 patch_coords     (1, 4194304,2) f32   8388608
//  3 elevation_angle  (1, 4194304,1) f32   4194304
//  4 init_elevation   (1, 4194304,1) f32   4194304
//  5 target_coords    (1, 4194304,2) f32   8388608
//  6 src_idx          (4194304,)     i32
//  7 tgt_idx          (4194304,)     i32
//  8 patch_idx        (4194304,)     i32
// Output: [residual_proj (2E) | residual_pose (57344) | residual_elev (E)]

#define R_MIN   0.5f
#define R_MAX   30.0f
#define BINS    512.0f
#define BEAMS   512.0f
#define FOV_H   2.0943951f

__global__ __launch_bounds__(256) void ba_kernel(
    const float*  __restrict__ poses,
    const float*  __restrict__ init_poses,
    const float*  __restrict__ patch_coords,   // float2 per patch
    const float*  __restrict__ elev,
    const float*  __restrict__ init_elev,
    const float*  __restrict__ target,         // float2 per edge
    const int*    __restrict__ src_idx,
    const int*    __restrict__ tgt_idx,
    const int*    __restrict__ patch_idx,
    float*        __restrict__ out,
    int E, int P7)
{
    const int e = blockIdx.x * blockDim.x + threadIdx.x;
    if (e >= E) return;

    const long long proj_elems = 2LL * E;
    // ---- residual_pose (first 57344 threads) ----
    if (e < P7) {
        out[proj_elems + e] = poses[e] - init_poses[e];
    }
    // ---- residual_elev (sequential) ----
    out[proj_elems + P7 + e] = elev[e] - init_elev[e];

    // ---- residual_proj ----
    const int p = __ldg(patch_idx + e);
    const int s = __ldg(src_idx  + e);
    const int t = __ldg(tgt_idx  + e);

    const float2 pc = __ldg(((const float2*)patch_coords) + p);  // (r, theta)
    const float  ph = __ldg(elev + p);                            // phi

    // polar -> cart
    float st, ct, sph, cph;
    __sincosf(pc.y, &st, &ct);
    __sincosf(ph,   &sph, &cph);
    const float rcp = pc.x * cph;
    float vx = rcp * ct;
    float vy = rcp * st;
    float vz = pc.x * sph;

    // src pose
    const float* sp = poses + 7 * s;
    const float stx = __ldg(sp + 0), sty = __ldg(sp + 1), stz = __ldg(sp + 2);
    const float sqx = __ldg(sp + 3), sqy = __ldg(sp + 4), sqz = __ldg(sp + 5), sqw = __ldg(sp + 6);

    // rotate by src quat: v' = v + w*tvec + u x tvec, tvec = 2 u x v
    {
        const float tx = 2.0f * (sqy * vz - sqz * vy);
        const float ty = 2.0f * (sqz * vx - sqx * vz);
        const float tz = 2.0f * (sqx * vy - sqy * vx);
        const float rx = vx + sqw * tx + (sqy * tz - sqz * ty);
        const float ry = vy + sqw * ty + (sqz * tx - sqx * tz);
        const float rz = vz + sqw * tz + (sqx * ty - sqy * tx);
        vx = rx + stx; vy = ry + sty; vz = rz + stz;   // global
    }

    // tgt pose
    const float* tp = poses + 7 * t;
    const float ttx = __ldg(tp + 0), tty = __ldg(tp + 1), ttz = __ldg(tp + 2);
    // inverse quat: (-x,-y,-z,w)
    const float tqx = -__ldg(tp + 3), tqy = -__ldg(tp + 4), tqz = -__ldg(tp + 5), tqw = __ldg(tp + 6);

    vx -= ttx; vy -= tty; vz -= ttz;
    float lx, ly, lz;
    {
        const float tx = 2.0f * (tqy * vz - tqz * vy);
        const float ty = 2.0f * (tqz * vx - tqx * vz);
        const float tz = 2.0f * (tqx * vy - tqy * vx);
        lx = vx + tqw * tx + (tqy * tz - tqz * ty);
        ly = vy + tqw * ty + (tqz * tx - tqx * tz);
        lz = vz + tqw * tz + (tqx * ty - tqy * tx);
    }

    // cart -> polar: only r and theta are consumed downstream
    const float r3 = sqrtf(lx * lx + ly * ly + lz * lz);
    const float th = atan2f(ly, lx);

    const float2 tg = __ldg(((const float2*)target) + e);
    float2 res;
    res.x = (r3 - tg.x) * (BINS  / (R_MAX - R_MIN));
    res.y = (th - tg.y) * (BEAMS / FOV_H);
    ((float2*)out)[e] = res;
}

extern "C" void kernel_launch(void* const* d_in, const int* in_sizes, int n_in,
                              void* d_out, int out_size)
{
    const float* poses        = (const float*)d_in[0];
    const float* init_poses   = (const float*)d_in[1];
    const float* patch_coords = (const float*)d_in[2];
    const float* elev         = (const float*)d_in[3];
    const float* init_elev    = (const float*)d_in[4];
    const float* target       = (const float*)d_in[5];
    const int*   src_idx      = (const int*)d_in[6];
    const int*   tgt_idx      = (const int*)d_in[7];
    const int*   patch_idx    = (const int*)d_in[8];
    float*       out          = (float*)d_out;

    const int E  = in_sizes[8];   // 4194304
    const int P7 = in_sizes[0];   // 57344

    const int threads = 256;
    const int blocks  = (E + threads - 1) / threads;
    ba_kernel<<<blocks, threads>>>(poses, init_poses, patch_coords, elev,
                                   init_elev, target, src_idx, tgt_idx,
                                   patch_idx, out, E, P7);
}

// round 2
// speedup vs baseline: 1.1972x; 1.1972x over previous
#include <cuda_runtime.h>
#include <cuda_bf16.h>

// BundleAdjustment, round 2: widen divergent gathers.
// Prepass A: pack poses (stride 7 -> padded 8 floats) + pose residual.
// Prepass B: pack (r, theta, phi) into float4 + elev residual.
// Main: 1x LDG.128 patch gather + 2x2 LDG.128 pose gathers.

#define R_MIN   0.5f
#define R_MAX   30.0f
#define BINS    512.0f
#define BEAMS   512.0f
#define FOV_H   2.0943951f

#define E_NUM   4194304
#define P_NUM   8192

// Scratch (device globals -- allocation-free per harness rules)
__device__ float4 g_patch_packed[E_NUM];      // 64 MB: (r, theta, phi, 0)
__device__ float4 g_pose_packed[2 * P_NUM];   // 256 KB: [2i]=(tx,ty,tz,qx) [2i+1]=(qy,qz,qw,0)

// ---------------- Prepass A: poses ----------------
__global__ __launch_bounds__(256) void pose_prepass(
    const float* __restrict__ poses,
    const float* __restrict__ init_poses,
    float*       __restrict__ out,          // out + 2E (pose residual region)
    int P7)
{
    const int i = blockIdx.x * blockDim.x + threadIdx.x;
    if (i < P7) out[i] = poses[i] - init_poses[i];
    if (i < P_NUM) {
        const float* p = poses + 7 * i;
        g_pose_packed[2 * i]     = make_float4(p[0], p[1], p[2], p[3]);
        g_pose_packed[2 * i + 1] = make_float4(p[4], p[5], p[6], 0.0f);
    }
}

// ---------------- Prepass B: patch pack + elev residual ----------------
__global__ __launch_bounds__(256) void patch_prepass(
    const float* __restrict__ patch_coords,  // float2 per patch
    const float* __restrict__ elev,
    const float* __restrict__ init_elev,
    float*       __restrict__ out_elev,      // out + 2E + P7 (elev residual region)
    int E)
{
    const int i = blockIdx.x * blockDim.x + threadIdx.x;
    if (i >= E) return;
    const float2 pc = __ldg(((const float2*)patch_coords) + i);
    const float  ph = __ldg(elev + i);
    g_patch_packed[i] = make_float4(pc.x, pc.y, ph, 0.0f);
    out_elev[i] = ph - __ldg(init_elev + i);
}

// ---------------- Main: reprojection residual ----------------
__global__ __launch_bounds__(256) void ba_main(
    const float* __restrict__ target,       // float2 per edge
    const int*   __restrict__ src_idx,
    const int*   __restrict__ tgt_idx,
    const int*   __restrict__ patch_idx,
    float*       __restrict__ out,          // residual_proj region (float2 per edge)
    int E)
{
    const int e = blockIdx.x * blockDim.x + threadIdx.x;
    if (e >= E) return;

    const int p = __ldg(patch_idx + e);
    const int s = __ldg(src_idx  + e);
    const int t = __ldg(tgt_idx  + e);

    const float4 pk = g_patch_packed[p];     // r, theta, phi

    // polar -> cart
    float st, ct, sph, cph;
    __sincosf(pk.y, &st, &ct);
    __sincosf(pk.z, &sph, &cph);
    const float rcp = pk.x * cph;
    float vx = rcp * ct;
    float vy = rcp * st;
    float vz = pk.x * sph;

    // src pose (2x LDG.128)
    const float4 sa = g_pose_packed[2 * s];
    const float4 sb = g_pose_packed[2 * s + 1];
    // sa = (tx,ty,tz,qx), sb = (qy,qz,qw,-)
    {
        const float qx = sa.w, qy = sb.x, qz = sb.y, qw = sb.z;
        const float tx = 2.0f * (qy * vz - qz * vy);
        const float ty = 2.0f * (qz * vx - qx * vz);
        const float tz = 2.0f * (qx * vy - qy * vx);
        const float rx = vx + qw * tx + (qy * tz - qz * ty);
        const float ry = vy + qw * ty + (qz * tx - qx * tz);
        const float rz = vz + qw * tz + (qx * ty - qy * tx);
        vx = rx + sa.x; vy = ry + sa.y; vz = rz + sa.z;   // global frame
    }

    // tgt pose (2x LDG.128), inverse rotation
    const float4 ta = g_pose_packed[2 * t];
    const float4 tb = g_pose_packed[2 * t + 1];
    vx -= ta.x; vy -= ta.y; vz -= ta.z;
    float lx, ly, lz;
    {
        const float qx = -ta.w, qy = -tb.x, qz = -tb.y, qw = tb.z;
        const float tx = 2.0f * (qy * vz - qz * vy);
        const float ty = 2.0f * (qz * vx - qx * vz);
        const float tz = 2.0f * (qx * vy - qy * vx);
        lx = vx + qw * tx + (qy * tz - qz * ty);
        ly = vy + qw * ty + (qz * tx - qx * tz);
        lz = vz + qw * tz + (qx * ty - qy * tx);
    }

    const float r3 = sqrtf(lx * lx + ly * ly + lz * lz);
    const float th = atan2f(ly, lx);

    const float2 tg = __ldg(((const float2*)target) + e);
    float2 res;
    res.x = (r3 - tg.x) * (BINS  / (R_MAX - R_MIN));
    res.y = (th - tg.y) * (BEAMS / FOV_H);
    ((float2*)out)[e] = res;
}

extern "C" void kernel_launch(void* const* d_in, const int* in_sizes, int n_in,
                              void* d_out, int out_size)
{
    const float* poses        = (const float*)d_in[0];
    const float* init_poses   = (const float*)d_in[1];
    const float* patch_coords = (const float*)d_in[2];
    const float* elev         = (const float*)d_in[3];
    const float* init_elev    = (const float*)d_in[4];
    const float* target       = (const float*)d_in[5];
    const int*   src_idx      = (const int*)d_in[6];
    const int*   tgt_idx      = (const int*)d_in[7];
    const int*   patch_idx    = (const int*)d_in[8];
    float*       out          = (float*)d_out;

    const int E  = in_sizes[8];   // 4194304
    const int P7 = in_sizes[0];   // 57344
    const long long proj_elems = 2LL * E;

    const int threads = 256;

    pose_prepass<<<(P7 + threads - 1) / threads, threads>>>(
        poses, init_poses, out + proj_elems, P7);

    patch_prepass<<<(E + threads - 1) / threads, threads>>>(
        patch_coords, elev, init_elev, out + proj_elems + P7, E);

    ba_main<<<(E + threads - 1) / threads, threads>>>(
        target, src_idx, tgt_idx, patch_idx, out, E);
}

// round 3
// speedup vs baseline: 1.2544x; 1.0478x over previous
#include <cuda_runtime.h>
#include <cuda_bf16.h>

// BundleAdjustment, round 3:
//  - single fused prepass (pose pack + pose residual + patch local-cart pack + elev residual)
//  - scratch holds precomputed LOCAL CARTESIAN point per patch (trig moved out of main)
//  - main kernel processes 2 edges/thread with vectorized sequential accesses

#define R_MIN   0.5f
#define R_MAX   30.0f
#define BINS    512.0f
#define BEAMS   512.0f
#define FOV_H   2.0943951f

#define E_NUM   4194304
#define P_NUM   8192

// Scratch (device globals -- allocation-free per harness rules)
__device__ float4 g_patch_cart[E_NUM];        // 64 MB: local cartesian (x, y, z, 0)
__device__ float4 g_pose_packed[2 * P_NUM];   // 256 KB: [2i]=(tx,ty,tz,qx) [2i+1]=(qy,qz,qw,0)

// ---------------- Fused prepass ----------------
// grid covers E/4 threads; each thread does 4 grid-strided patches.
// Threads with global id < P7 additionally handle pose residual; id < P_NUM pack poses.
__global__ __launch_bounds__(256) void prepass(
    const float* __restrict__ poses,
    const float* __restrict__ init_poses,
    const float* __restrict__ patch_coords,  // float2 per patch
    const float* __restrict__ elev,
    const float* __restrict__ init_elev,
    float*       __restrict__ out_pose,      // out + 2E
    float*       __restrict__ out_elev,      // out + 2E + P7
    int E, int P7)
{
    const int tid    = blockIdx.x * blockDim.x + threadIdx.x;
    const int stride = gridDim.x * blockDim.x;

    // pose residual + pose packing (tiny, first blocks only)
    if (tid < P7) out_pose[tid] = poses[tid] - init_poses[tid];
    if (tid < P_NUM) {
        const float* p = poses + 7 * tid;
        g_pose_packed[2 * tid]     = make_float4(p[0], p[1], p[2], p[3]);
        g_pose_packed[2 * tid + 1] = make_float4(p[4], p[5], p[6], 0.0f);
    }

    // patch pack + elev residual, 4-way grid-stride for MLP
    #pragma unroll 4
    for (int i = tid; i < E; i += stride) {
        const float2 pc = __ldg(((const float2*)patch_coords) + i);
        const float  ph = __ldg(elev + i);
        out_elev[i] = ph - __ldg(init_elev + i);

        float st, ct, sph, cph;
        __sincosf(pc.y, &st, &ct);
        __sincosf(ph,   &sph, &cph);
        const float rcp = pc.x * cph;
        g_patch_cart[i] = make_float4(rcp * ct, rcp * st, pc.x * sph, 0.0f);
    }
}

// ---------------- Main: reprojection residual, 2 edges/thread ----------------
__device__ __forceinline__ float2 project_one(int p, int s, int t, float2 tg)
{
    const float4 pk = __ldg(&g_patch_cart[p]);   // local cartesian
    float vx = pk.x, vy = pk.y, vz = pk.z;

    // src pose: rotate + translate
    const float4 sa = __ldg(&g_pose_packed[2 * s]);
    const float4 sb = __ldg(&g_pose_packed[2 * s + 1]);
    {
        const float qx = sa.w, qy = sb.x, qz = sb.y, qw = sb.z;
        const float tx = 2.0f * (qy * vz - qz * vy);
        const float ty = 2.0f * (qz * vx - qx * vz);
        const float tz = 2.0f * (qx * vy - qy * vx);
        const float rx = vx + qw * tx + (qy * tz - qz * ty);
        const float ry = vy + qw * ty + (qz * tx - qx * tz);
        const float rz = vz + qw * tz + (qx * ty - qy * tx);
        vx = rx + sa.x; vy = ry + sa.y; vz = rz + sa.z;
    }

    // tgt pose: translate + inverse rotate
    const float4 ta = __ldg(&g_pose_packed[2 * t]);
    const float4 tb = __ldg(&g_pose_packed[2 * t + 1]);
    vx -= ta.x; vy -= ta.y; vz -= ta.z;
    float lx, ly, lz;
    {
        const float qx = -ta.w, qy = -tb.x, qz = -tb.y, qw = tb.z;
        const float tx = 2.0f * (qy * vz - qz * vy);
        const float ty = 2.0f * (qz * vx - qx * vz);
        const float tz = 2.0f * (qx * vy - qy * vx);
        lx = vx + qw * tx + (qy * tz - qz * ty);
        ly = vy + qw * ty + (qz * tx - qx * tz);
        lz = vz + qw * tz + (qx * ty - qy * tx);
    }

    const float r3 = sqrtf(lx * lx + ly * ly + lz * lz);
    const float th = atan2f(ly, lx);

    float2 res;
    res.x = (r3 - tg.x) * (BINS  / (R_MAX - R_MIN));
    res.y = (th - tg.y) * (BEAMS / FOV_H);
    return res;
}

__global__ __launch_bounds__(256) void ba_main(
    const float* __restrict__ target,       // float2 per edge
    const int*   __restrict__ src_idx,
    const int*   __restrict__ tgt_idx,
    const int*   __restrict__ patch_idx,
    float*       __restrict__ out,          // residual_proj (float2 per edge)
    int E)
{
    const int tid = blockIdx.x * blockDim.x + threadIdx.x;
    const int e0  = 2 * tid;
    if (e0 + 1 < E) {
        const int2   sp = __ldg(((const int2*)src_idx)   + tid);
        const int2   tp = __ldg(((const int2*)tgt_idx)   + tid);
        const int2   pp = __ldg(((const int2*)patch_idx) + tid);
        const float4 tg = __ldg(((const float4*)target)  + tid);

        const float2 r0 = project_one(pp.x, sp.x, tp.x, make_float2(tg.x, tg.y));
        const float2 r1 = project_one(pp.y, sp.y, tp.y, make_float2(tg.z, tg.w));

        ((float4*)out)[tid] = make_float4(r0.x, r0.y, r1.x, r1.y);
    } else if (e0 < E) {
        // tail (E odd)
        const int s = __ldg(src_idx + e0), t = __ldg(tgt_idx + e0), p = __ldg(patch_idx + e0);
        const float2 tg = __ldg(((const float2*)target) + e0);
        ((float2*)out)[e0] = project_one(p, s, t, tg);
    }
}

extern "C" void kernel_launch(void* const* d_in, const int* in_sizes, int n_in,
                              void* d_out, int out_size)
{
    const float* poses        = (const float*)d_in[0];
    const float* init_poses   = (const float*)d_in[1];
    const float* patch_coords = (const float*)d_in[2];
    const float* elev         = (const float*)d_in[3];
    const float* init_elev    = (const float*)d_in[4];
    const float* target       = (const float*)d_in[5];
    const int*   src_idx      = (const int*)d_in[6];
    const int*   tgt_idx      = (const int*)d_in[7];
    const int*   patch_idx    = (const int*)d_in[8];
    float*       out          = (float*)d_out;

    const int E  = in_sizes[8];   // 4194304
    const int P7 = in_sizes[0];   // 57344
    const long long proj_elems = 2LL * E;

    const int threads = 256;

    // prepass: E/4 threads, 4-way grid-stride
    const int pre_threads_total = (E + 3) / 4;
    const int pre_blocks = (pre_threads_total + threads - 1) / threads;
    prepass<<<pre_blocks, threads>>>(
        poses, init_poses, patch_coords, elev, init_elev,
        out + proj_elems, out + proj_elems + P7, E, P7);

    // main: 2 edges per thread
    const int pairs = (E + 1) / 2;
    const int main_blocks = (pairs + threads - 1) / threads;
    ba_main<<<main_blocks, threads>>>(
        target, src_idx, tgt_idx, patch_idx, out, E);
}